// round 8
// baseline (speedup 1.0000x reference)
#include <cuda_runtime.h>
#include <cuda_fp16.h>
#include <stdint.h>

// Problem constants (fixed by setup_inputs)
#define NPOI    50000
#define DIM     256
#define D4      (DIM / 4)            // 64 float4 per row (fp32)
#define D16     (DIM / 8)            // 32 uint4 per row (fp16)
#define NELEM   (NPOI * DIM)
#define NV4     (NELEM / 4)
#define NNZ_MAX 1600000
#define MASKB   (NELEM / 8)          // mask bytes per layer (1.6M)
#define THRESH  0xE6666600u          // bits < THRESH <=> uniform(bits) < 0.9f
#define KEEP_INV (1.0f / 0.9f)
// mask-generation row ranges
#define M1      6016                 // [0,M1)    x3 layers -> hist2
#define M2      17024                // [M1,M2)   x3 layers -> scatter2
#define M3      31488                // [M2,M3)   per layer -> spmm_h
                                     // [M3,NPOI) per layer -> fused inline

// ---------------- scratch (static device globals) ---------------------------
__device__ uint4    g_p16[NPOI * D16];   // poi in fp16 (layer-0 gather)
__device__ uint4    g_x1[NPOI * D16];    // x_1 fp16
__device__ uint4    g_x2[NPOI * D16];    // x_2 fp16
__device__ uint4    g_mt16[NPOI * D16];  // msg_tar fp16
__device__ uint8_t  g_mask[3 * MASKB];   // dropout mask bits, 3 layers
__device__ int      g_rp_src[NPOI + 1], g_rp_tar[NPOI + 1];
__device__ int      g_cnt[2 * NPOI];
__device__ uint32_t g_rr_t[NNZ_MAX], g_rr_s[NNZ_MAX];  // (row<<16)|rank
__device__ uint32_t g_e_src[NNZ_MAX], g_e_tar[NNZ_MAX]; // (valh<<16)|col

// ---------------- fp16 helpers ----------------------------------------------
__device__ __forceinline__ float edge_val(uint32_t rec)
{
    __half_raw hr; hr.x = (unsigned short)(rec >> 16);
    return __half2float((__half)hr);
}

__device__ __forceinline__ void acc8(float* a, float v, uint4 q)
{
    float2 f;
    f = __half22float2(*(__half2*)&q.x); a[0] = fmaf(v, f.x, a[0]); a[1] = fmaf(v, f.y, a[1]);
    f = __half22float2(*(__half2*)&q.y); a[2] = fmaf(v, f.x, a[2]); a[3] = fmaf(v, f.y, a[3]);
    f = __half22float2(*(__half2*)&q.z); a[4] = fmaf(v, f.x, a[4]); a[5] = fmaf(v, f.y, a[5]);
    f = __half22float2(*(__half2*)&q.w); a[6] = fmaf(v, f.x, a[6]); a[7] = fmaf(v, f.y, a[7]);
}

__device__ __forceinline__ void unpack8(float* f, uint4 q)
{
    float2 t;
    t = __half22float2(*(__half2*)&q.x); f[0] = t.x; f[1] = t.y;
    t = __half22float2(*(__half2*)&q.y); f[2] = t.x; f[3] = t.y;
    t = __half22float2(*(__half2*)&q.z); f[4] = t.x; f[5] = t.y;
    t = __half22float2(*(__half2*)&q.w); f[6] = t.x; f[7] = t.y;
}

__device__ __forceinline__ uint4 pack8(const float* a)
{
    uint4 o;
    __half2 h;
    h = __floats2half2_rn(a[0], a[1]); o.x = *(uint32_t*)&h;
    h = __floats2half2_rn(a[2], a[3]); o.y = *(uint32_t*)&h;
    h = __floats2half2_rn(a[4], a[5]); o.z = *(uint32_t*)&h;
    h = __floats2half2_rn(a[6], a[7]); o.w = *(uint32_t*)&h;
    return o;
}

// ---------------- Threefry-2x32 (JAX partitionable random_bits) -------------
__device__ __forceinline__ uint32_t tf_bits(uint32_t k0, uint32_t k1,
                                            uint32_t k2, uint32_t ctr)
{
    uint32_t x0 = k0;
    uint32_t x1 = ctr + k1;
#define TFR(r) { x0 += x1; x1 = __funnelshift_l(x1, x1, (r)); x1 ^= x0; }
    TFR(13) TFR(15) TFR(26) TFR(6)    x0 += k1; x1 += k2 + 1u;
    TFR(17) TFR(29) TFR(16) TFR(24)   x0 += k2; x1 += k0 + 2u;
    TFR(13) TFR(15) TFR(26) TFR(6)    x0 += k0; x1 += k1 + 3u;
    TFR(17) TFR(29) TFR(16) TFR(24)   x0 += k1; x1 += k2 + 4u;
    TFR(13) TFR(15) TFR(26) TFR(6)    x0 += k2; x1 += k0 + 5u;
#undef TFR
    return x0 ^ x1;
}

__device__ __forceinline__ uint32_t mask8(uint32_t k0, uint32_t k1,
                                          uint32_t k2, uint32_t base)
{
    uint32_t m = 0;
    #pragma unroll
    for (int t = 0; t < 8; t++)
        m |= (tf_bits(k0, k1, k2, base + (uint32_t)t) < THRESH) ? (1u << t) : 0u;
    return m;
}

__device__ __forceinline__ void pick_key(int layer,
    uint32_t a0, uint32_t b0, uint32_t a1, uint32_t b1,
    uint32_t a2, uint32_t b2, uint32_t* k0, uint32_t* k1)
{
    *k0 = (layer == 0) ? a0 : (layer == 1) ? a1 : a2;
    *k1 = (layer == 0) ? b0 : (layer == 1) ? b1 : b2;
}

// -- CSR build: histogram (rank via atomic return, packed with row) + cvt ----
// thread t: one edge pair, one fp16 conversion element, mask rows [0,M1)x3
__global__ void __launch_bounds__(256) hist2_kernel(
    const int* __restrict__ tar_rows, const int* __restrict__ src_rows,
    int* __restrict__ cnt, uint32_t* __restrict__ rr_t, uint32_t* __restrict__ rr_s,
    const float4* __restrict__ poi, uint4* __restrict__ p16,
    uint8_t* __restrict__ mask, int nnz,
    uint32_t a0, uint32_t b0, uint32_t a1, uint32_t b1, uint32_t a2, uint32_t b2)
{
    int t = blockIdx.x * 256 + threadIdx.x;
    if (t < nnz) {
        int rt_row = __ldg(tar_rows + t);
        int rs_row = __ldg(src_rows + t);
        int rt = atomicAdd(cnt + rt_row, 1);
        int rs = atomicAdd(cnt + NPOI + rs_row, 1);
        __stcs(rr_t + t, ((uint32_t)rt_row << 16) | (uint32_t)rt);
        __stcs(rr_s + t, ((uint32_t)rs_row << 16) | (uint32_t)rs);
    }
    if (t < NPOI * D16) {
        float4 a = __ldg(poi + t * 2), b = __ldg(poi + t * 2 + 1);
        float v[8] = {a.x, a.y, a.z, a.w, b.x, b.y, b.z, b.w};
        p16[t] = pack8(v);
    }
    if (t < 3 * M1 * 32) {
        int layer = t / (M1 * 32);
        int r     = t - layer * (M1 * 32);
        uint32_t k0, k1;
        pick_key(layer, a0, b0, a1, b1, a2, b2, &k0, &k1);
        uint32_t k2 = k0 ^ k1 ^ 0x1BD11BDAu;
        mask[layer * MASKB + r] = (uint8_t)mask8(k0, k1, k2, (uint32_t)r * 8u);
    }
}

// ---------------- CSR build: 2-block exclusive scan -------------------------
__global__ void __launch_bounds__(1024) scan2_kernel(
    const int* __restrict__ cnt, int* __restrict__ rp_t, int* __restrict__ rp_s)
{
    const int* c  = (blockIdx.x == 0) ? cnt  : cnt + NPOI;
    int* rowptr   = (blockIdx.x == 0) ? rp_t : rp_s;
    const int n = NPOI;

    __shared__ int carry;
    __shared__ int wsum[32];
    int tid = threadIdx.x, lane = tid & 31, wid = tid >> 5;
    if (tid == 0) carry = 0;
    __syncthreads();
    for (int base = 0; base < n; base += 1024) {
        int c0 = carry;
        int i = base + tid;
        int v = (i < n) ? c[i] : 0;
        int inc = v;
        #pragma unroll
        for (int o = 1; o < 32; o <<= 1) {
            int t = __shfl_up_sync(0xFFFFFFFFu, inc, o);
            if (lane >= o) inc += t;
        }
        if (lane == 31) wsum[wid] = inc;
        __syncthreads();
        if (wid == 0) {
            int s = wsum[lane];
            #pragma unroll
            for (int o = 1; o < 32; o <<= 1) {
                int t = __shfl_up_sync(0xFFFFFFFFu, s, o);
                if (lane >= o) s += t;
            }
            wsum[lane] = s;
        }
        __syncthreads();
        int block_incl = inc + (wid ? wsum[wid - 1] : 0);
        if (i < n) rowptr[i] = c0 + block_incl - v;
        __syncthreads();
        if (tid == 1023) carry = c0 + block_incl;
        __syncthreads();
    }
    if (tid == 0) rowptr[n] = carry;
}

// --- CSR build: rank-based scatter (4B records) + mask rows [M1,M2) ---------
__global__ void __launch_bounds__(256) scatter2_kernel(
    const int* __restrict__ tar_cols, const float* __restrict__ tar_vals,
    const int* __restrict__ src_cols, const float* __restrict__ src_vals,
    const int* __restrict__ rp_t, const int* __restrict__ rp_s,
    const uint32_t* __restrict__ rr_t, const uint32_t* __restrict__ rr_s,
    uint32_t* __restrict__ et, uint32_t* __restrict__ es,
    uint8_t* __restrict__ mask, int nnz,
    uint32_t a0, uint32_t b0, uint32_t a1, uint32_t b1, uint32_t a2, uint32_t b2)
{
    int t = blockIdx.x * 256 + threadIdx.x;
    if (t < nnz) {
        {
            uint32_t rr = __ldcs(rr_t + t);
            int pos = __ldg(rp_t + (rr >> 16)) + (int)(rr & 0xFFFFu);
            __half hv = __float2half_rn(__ldg(tar_vals + t));
            et[pos] = (uint32_t)__ldg(tar_cols + t)
                    | ((uint32_t)__half_as_ushort(hv) << 16);
        }
        {
            uint32_t rr = __ldcs(rr_s + t);
            int pos = __ldg(rp_s + (rr >> 16)) + (int)(rr & 0xFFFFu);
            __half hv = __float2half_rn(__ldg(src_vals + t));
            es[pos] = (uint32_t)__ldg(src_cols + t)
                    | ((uint32_t)__half_as_ushort(hv) << 16);
        }
    }
    const int RANGE = (M2 - M1) * 32;
    if (t < 3 * RANGE) {
        int layer = t / RANGE;
        int r     = M1 * 32 + (t - layer * RANGE);
        uint32_t k0, k1;
        pick_key(layer, a0, b0, a1, b1, a2, b2, &k0, &k1);
        uint32_t k2 = k0 ^ k1 ^ 0x1BD11BDAu;
        mask[layer * MASKB + r] = (uint8_t)mask8(k0, k1, k2, (uint32_t)r * 8u);
    }
}

// ------- tar SpMM (fp16 operand, 4B edges) + mask rows [M2,M3) --------------
__global__ void __launch_bounds__(256) spmm_h(
    const int* __restrict__ rowptr, const uint32_t* __restrict__ edges,
    const uint4* __restrict__ X, uint4* __restrict__ Y,
    uint8_t* __restrict__ maskL, uint32_t k0, uint32_t k1)
{
    int row = blockIdx.x * 8 + (threadIdx.x >> 5);
    int g   = threadIdx.x & 31;
    int s = __ldg(rowptr + row), e = __ldg(rowptr + row + 1);
    float m[8] = {0.f, 0.f, 0.f, 0.f, 0.f, 0.f, 0.f, 0.f};
    int j = s;
    for (; j + 3 < e; j += 4) {
        uint32_t e0 = __ldcs(edges + j),     e1 = __ldcs(edges + j + 1);
        uint32_t e2 = __ldcs(edges + j + 2), e3 = __ldcs(edges + j + 3);
        uint4 a0 = __ldg(X + (size_t)(e0 & 0xFFFFu) * D16 + g);
        uint4 a1 = __ldg(X + (size_t)(e1 & 0xFFFFu) * D16 + g);
        uint4 a2 = __ldg(X + (size_t)(e2 & 0xFFFFu) * D16 + g);
        uint4 a3 = __ldg(X + (size_t)(e3 & 0xFFFFu) * D16 + g);
        acc8(m, edge_val(e0), a0);
        acc8(m, edge_val(e1), a1);
        acc8(m, edge_val(e2), a2);
        acc8(m, edge_val(e3), a3);
    }
    for (; j < e; j++) {
        uint32_t e0 = __ldcs(edges + j);
        uint4 a0 = __ldg(X + (size_t)(e0 & 0xFFFFu) * D16 + g);
        acc8(m, edge_val(e0), a0);
    }
    Y[(size_t)row * D16 + g] = pack8(m);

    if (row >= M2 && row < M3) {
        uint32_t k2 = k0 ^ k1 ^ 0x1BD11BDAu;
        uint32_t r = (uint32_t)(row * 32 + g);
        maskL[r] = (uint8_t)mask8(k0, k1, k2, r * 8u);
    }
}

// --- src SpMM fused: residual + dropout + deferred-mean epilogue ------------
// mode 0: v = drop(msg+poi);   x1 = v            (residual = poi f32)
// mode 1: v = drop(msg+x1);    x2 = v            (residual = x1 fp16)
// mode 2: v = drop(msg+x2);    out = (poi + x1 + x2 + v) * 0.25
__global__ void __launch_bounds__(256) spmm_h_fused(
    const int* __restrict__ rowptr, const uint32_t* __restrict__ edges,
    const uint4* __restrict__ X, const uint8_t* __restrict__ maskL,
    const float4* __restrict__ poi, const uint4* __restrict__ res16,
    const uint4* __restrict__ aux16, uint4* __restrict__ xout16,
    float4* __restrict__ out, uint32_t k0, uint32_t k1, int mode)
{
    int row = blockIdx.x * 8 + (threadIdx.x >> 5);
    int g   = threadIdx.x & 31;
    int s = __ldg(rowptr + row), e = __ldg(rowptr + row + 1);

    uint32_t m8;
    if (row < M3) {
        m8 = maskL[row * 32 + g];
    } else {
        uint32_t k2 = k0 ^ k1 ^ 0x1BD11BDAu;
        m8 = mask8(k0, k1, k2, (uint32_t)(row * DIM + g * 8));
    }

    float m[8] = {0.f, 0.f, 0.f, 0.f, 0.f, 0.f, 0.f, 0.f};
    int j = s;
    for (; j + 3 < e; j += 4) {
        uint32_t e0 = __ldcs(edges + j),     e1 = __ldcs(edges + j + 1);
        uint32_t e2 = __ldcs(edges + j + 2), e3 = __ldcs(edges + j + 3);
        uint4 a0 = __ldg(X + (size_t)(e0 & 0xFFFFu) * D16 + g);
        uint4 a1 = __ldg(X + (size_t)(e1 & 0xFFFFu) * D16 + g);
        uint4 a2 = __ldg(X + (size_t)(e2 & 0xFFFFu) * D16 + g);
        uint4 a3 = __ldg(X + (size_t)(e3 & 0xFFFFu) * D16 + g);
        acc8(m, edge_val(e0), a0);
        acc8(m, edge_val(e1), a1);
        acc8(m, edge_val(e2), a2);
        acc8(m, edge_val(e3), a3);
    }
    for (; j < e; j++) {
        uint32_t e0 = __ldcs(edges + j);
        uint4 a0 = __ldg(X + (size_t)(e0 & 0xFFFFu) * D16 + g);
        acc8(m, edge_val(e0), a0);
    }

    size_t i4  = (size_t)row * D4 + g * 2;
    size_t i16 = (size_t)row * D16 + g;

    float pv[8];
    if (mode == 0) {
        float4 p0 = __ldg(poi + i4), p1 = __ldg(poi + i4 + 1);
        pv[0] = p0.x; pv[1] = p0.y; pv[2] = p0.z; pv[3] = p0.w;
        pv[4] = p1.x; pv[5] = p1.y; pv[6] = p1.z; pv[7] = p1.w;
    } else {
        unpack8(pv, res16[i16]);
    }

    float v[8];
    #pragma unroll
    for (int t = 0; t < 8; t++)
        v[t] = ((m8 >> t) & 1u) ? (m[t] + pv[t]) * KEEP_INV : 0.0f;

    if (mode != 2) {
        xout16[i16] = pack8(v);
    } else {
        float4 p0 = __ldg(poi + i4), p1 = __ldg(poi + i4 + 1);
        float x1v[8];
        unpack8(x1v, aux16[i16]);
        // pv holds x2 (residual); v = v3
        out[i4] = make_float4(
            (p0.x + x1v[0] + pv[0] + v[0]) * 0.25f,
            (p0.y + x1v[1] + pv[1] + v[1]) * 0.25f,
            (p0.z + x1v[2] + pv[2] + v[2]) * 0.25f,
            (p0.w + x1v[3] + pv[3] + v[3]) * 0.25f);
        out[i4 + 1] = make_float4(
            (p1.x + x1v[4] + pv[4] + v[4]) * 0.25f,
            (p1.y + x1v[5] + pv[5] + v[5]) * 0.25f,
            (p1.z + x1v[6] + pv[6] + v[6]) * 0.25f,
            (p1.w + x1v[7] + pv[7] + v[7]) * 0.25f);
    }
}

// ---------------- host-side threefry (per-layer fold_in keys) ---------------
static inline unsigned h_rotl(unsigned x, int r) { return (x << r) | (x >> (32 - r)); }
static void host_threefry(unsigned k0, unsigned k1, unsigned x0, unsigned x1,
                          unsigned* o0, unsigned* o1)
{
    const int rots[2][4] = {{13, 15, 26, 6}, {17, 29, 16, 24}};
    unsigned ks[3] = {k0, k1, k0 ^ k1 ^ 0x1BD11BDAu};
    x0 += ks[0]; x1 += ks[1];
    for (int g = 0; g < 5; g++) {
        for (int j = 0; j < 4; j++) {
            x0 += x1; x1 = h_rotl(x1, rots[g & 1][j]); x1 ^= x0;
        }
        x0 += ks[(g + 1) % 3];
        x1 += ks[(g + 2) % 3] + (unsigned)(g + 1);
    }
    *o0 = x0; *o1 = x1;
}

extern "C" void kernel_launch(void* const* d_in, const int* in_sizes, int n_in,
                              void* d_out, int out_size)
{
    const float* poi     = (const float*)d_in[0];
    const int*   src_row = (const int*)  d_in[1];
    const int*   src_col = (const int*)  d_in[2];
    const float* src_val = (const float*)d_in[3];
    const int*   tar_row = (const int*)  d_in[4];
    const int*   tar_col = (const int*)  d_in[5];
    const float* tar_val = (const float*)d_in[6];
    int nnz = in_sizes[1];

    uint4 *p16, *x1, *x2, *mt16;
    uint8_t *mask;
    int *rp_s, *rp_t, *cnt;
    uint32_t *rr_t, *rr_s, *es, *et;
    cudaGetSymbolAddress((void**)&p16,  g_p16);
    cudaGetSymbolAddress((void**)&x1,   g_x1);
    cudaGetSymbolAddress((void**)&x2,   g_x2);
    cudaGetSymbolAddress((void**)&mt16, g_mt16);
    cudaGetSymbolAddress((void**)&mask, g_mask);
    cudaGetSymbolAddress((void**)&rp_s, g_rp_src);
    cudaGetSymbolAddress((void**)&rp_t, g_rp_tar);
    cudaGetSymbolAddress((void**)&cnt,  g_cnt);
    cudaGetSymbolAddress((void**)&rr_t, g_rr_t);
    cudaGetSymbolAddress((void**)&rr_s, g_rr_s);
    cudaGetSymbolAddress((void**)&es,   g_e_src);
    cudaGetSymbolAddress((void**)&et,   g_e_tar);

    unsigned lk0[3], lk1[3];
    for (unsigned i = 0; i < 3; i++)
        host_threefry(0u, 42u, 0u, i, &lk0[i], &lk1[i]);

    int nthreads = nnz > NPOI * D16 ? nnz : NPOI * D16;
    int eb = (nthreads + 255) / 256;
    int rb = NPOI / 8;

    // ---- fused CSR build (+ fp16 snapshot + mask rows [0,M2) x 3 layers) ---
    cudaMemsetAsync(cnt, 0, 2 * NPOI * sizeof(int), 0);
    hist2_kernel<<<eb, 256>>>(tar_row, src_row, cnt, rr_t, rr_s,
                              (const float4*)poi, p16, mask, nnz,
                              lk0[0], lk1[0], lk0[1], lk1[1], lk0[2], lk1[2]);
    scan2_kernel<<<2, 1024>>>(cnt, rp_t, rp_s);
    scatter2_kernel<<<eb, 256>>>(tar_col, tar_val, src_col, src_val,
                                 rp_t, rp_s, rr_t, rr_s, et, es, mask, nnz,
                                 lk0[0], lk1[0], lk0[1], lk1[1], lk0[2], lk1[2]);

    // ---- 3 layers (deferred mean; x_i kept in fp16 buffers) ----
    const uint4* gx[3]  = {p16, x1, x2};
    uint4*       xo[3]  = {x1, x2, nullptr};
    const uint4* res[3] = {nullptr, x1, x2};
    for (int i = 0; i < 3; i++) {
        uint8_t* maskL = mask + (size_t)i * MASKB;
        spmm_h<<<rb, 256>>>(rp_t, et, gx[i], mt16, maskL, lk0[i], lk1[i]);
        spmm_h_fused<<<rb, 256>>>(rp_s, es, mt16, maskL,
                                  (const float4*)poi, res[i], x1,
                                  xo[i], (float4*)d_out,
                                  lk0[i], lk1[i], i);
    }
}

// round 9
// speedup vs baseline: 1.0340x; 1.0340x over previous
#include <cuda_runtime.h>
#include <cuda_fp16.h>
#include <stdint.h>

// Problem constants (fixed by setup_inputs)
#define NPOI    50000
#define DIM     256
#define D4      (DIM / 4)            // 64 float4 per row (fp32)
#define D16     (DIM / 8)            // 32 uint4 per row (fp16)
#define NELEM   (NPOI * DIM)
#define NV4     (NELEM / 4)
#define NNZ_MAX 1600000
#define MASKB   (NELEM / 8)          // mask bytes per layer (1.6M)
#define THRESH  0xE6666600u          // bits < THRESH <=> uniform(bits) < 0.9f
#define KEEP_INV (1.0f / 0.9f)
// mask-generation row ranges (who computes which rows' dropout masks)
#define R1      9216                 // [0,R1)    x3 -> hist2
#define R2      17408                // [R1,R2)   x3 -> scan2 idle blocks
#define R3      29696                // [R2,R3)   x3 -> scatter2
#define R4      40960                // [R3,R4)   per layer -> spmm_h
                                     // [R4,NPOI) per layer -> fused inline

// ---------------- scratch (static device globals) ---------------------------
__device__ uint4    g_p16[NPOI * D16];   // poi in fp16 (layer-0 gather)
__device__ uint4    g_x1[NPOI * D16];    // x_1 fp16
__device__ uint4    g_x2[NPOI * D16];    // x_2 fp16
__device__ uint4    g_mt16[NPOI * D16];  // msg_tar fp16
__device__ uint8_t  g_mask[3 * MASKB];   // dropout mask bits, 3 layers
__device__ int      g_rp_src[NPOI + 1], g_rp_tar[NPOI + 1];
__device__ int      g_cnt[2 * NPOI];
__device__ uint32_t g_rr_t[NNZ_MAX], g_rr_s[NNZ_MAX];  // (row<<16)|rank
__device__ int2     g_e_src[NNZ_MAX], g_e_tar[NNZ_MAX]; // (col, val-bits f32)

// ---------------- fp16 helpers ----------------------------------------------
__device__ __forceinline__ void acc8(float* a, float v, uint4 q)
{
    float2 f;
    f = __half22float2(*(__half2*)&q.x); a[0] = fmaf(v, f.x, a[0]); a[1] = fmaf(v, f.y, a[1]);
    f = __half22float2(*(__half2*)&q.y); a[2] = fmaf(v, f.x, a[2]); a[3] = fmaf(v, f.y, a[3]);
    f = __half22float2(*(__half2*)&q.z); a[4] = fmaf(v, f.x, a[4]); a[5] = fmaf(v, f.y, a[5]);
    f = __half22float2(*(__half2*)&q.w); a[6] = fmaf(v, f.x, a[6]); a[7] = fmaf(v, f.y, a[7]);
}

__device__ __forceinline__ void unpack8(float* f, uint4 q)
{
    float2 t;
    t = __half22float2(*(__half2*)&q.x); f[0] = t.x; f[1] = t.y;
    t = __half22float2(*(__half2*)&q.y); f[2] = t.x; f[3] = t.y;
    t = __half22float2(*(__half2*)&q.z); f[4] = t.x; f[5] = t.y;
    t = __half22float2(*(__half2*)&q.w); f[6] = t.x; f[7] = t.y;
}

__device__ __forceinline__ uint4 pack8(const float* a)
{
    uint4 o;
    __half2 h;
    h = __floats2half2_rn(a[0], a[1]); o.x = *(uint32_t*)&h;
    h = __floats2half2_rn(a[2], a[3]); o.y = *(uint32_t*)&h;
    h = __floats2half2_rn(a[4], a[5]); o.z = *(uint32_t*)&h;
    h = __floats2half2_rn(a[6], a[7]); o.w = *(uint32_t*)&h;
    return o;
}

// ---------------- Threefry-2x32 (JAX partitionable random_bits) -------------
__device__ __forceinline__ uint32_t tf_bits(uint32_t k0, uint32_t k1,
                                            uint32_t k2, uint32_t ctr)
{
    uint32_t x0 = k0;
    uint32_t x1 = ctr + k1;
#define TFR(r) { x0 += x1; x1 = __funnelshift_l(x1, x1, (r)); x1 ^= x0; }
    TFR(13) TFR(15) TFR(26) TFR(6)    x0 += k1; x1 += k2 + 1u;
    TFR(17) TFR(29) TFR(16) TFR(24)   x0 += k2; x1 += k0 + 2u;
    TFR(13) TFR(15) TFR(26) TFR(6)    x0 += k0; x1 += k1 + 3u;
    TFR(17) TFR(29) TFR(16) TFR(24)   x0 += k1; x1 += k2 + 4u;
    TFR(13) TFR(15) TFR(26) TFR(6)    x0 += k2; x1 += k0 + 5u;
#undef TFR
    return x0 ^ x1;
}

__device__ __forceinline__ uint32_t mask8(uint32_t k0, uint32_t k1,
                                          uint32_t k2, uint32_t base)
{
    uint32_t m = 0;
    #pragma unroll
    for (int t = 0; t < 8; t++)
        m |= (tf_bits(k0, k1, k2, base + (uint32_t)t) < THRESH) ? (1u << t) : 0u;
    return m;
}

__device__ __forceinline__ void pick_key(int layer,
    uint32_t a0, uint32_t b0, uint32_t a1, uint32_t b1,
    uint32_t a2, uint32_t b2, uint32_t* k0, uint32_t* k1)
{
    *k0 = (layer == 0) ? a0 : (layer == 1) ? a1 : a2;
    *k1 = (layer == 0) ? b0 : (layer == 1) ? b1 : b2;
}

// -- CSR build: histogram (packed rank) + fp16 convert + mask [0,R1)x3 -------
__global__ void __launch_bounds__(256) hist2_kernel(
    const int* __restrict__ tar_rows, const int* __restrict__ src_rows,
    int* __restrict__ cnt, uint32_t* __restrict__ rr_t, uint32_t* __restrict__ rr_s,
    const float4* __restrict__ poi, uint4* __restrict__ p16,
    uint8_t* __restrict__ mask, int nnz,
    uint32_t a0, uint32_t b0, uint32_t a1, uint32_t b1, uint32_t a2, uint32_t b2)
{
    int t = blockIdx.x * 256 + threadIdx.x;
    if (t < nnz) {
        int rt_row = __ldg(tar_rows + t);
        int rs_row = __ldg(src_rows + t);
        int rt = atomicAdd(cnt + rt_row, 1);
        int rs = atomicAdd(cnt + NPOI + rs_row, 1);
        __stcs(rr_t + t, ((uint32_t)rt_row << 16) | (uint32_t)rt);
        __stcs(rr_s + t, ((uint32_t)rs_row << 16) | (uint32_t)rs);
    }
    if (t < NPOI * D16) {
        float4 a = __ldg(poi + t * 2), b = __ldg(poi + t * 2 + 1);
        float v[8] = {a.x, a.y, a.z, a.w, b.x, b.y, b.z, b.w};
        p16[t] = pack8(v);
    }
    if (t < 3 * R1 * 32) {
        int layer = t / (R1 * 32);
        int r     = t - layer * (R1 * 32);
        uint32_t k0, k1;
        pick_key(layer, a0, b0, a1, b1, a2, b2, &k0, &k1);
        uint32_t k2 = k0 ^ k1 ^ 0x1BD11BDAu;
        mask[layer * MASKB + r] = (uint8_t)mask8(k0, k1, k2, (uint32_t)r * 8u);
    }
}

// --- CSR build: 2-block exclusive scan; blocks >=2 generate mask [R1,R2)x3 --
__global__ void __launch_bounds__(1024) scan2_kernel(
    const int* __restrict__ cnt, int* __restrict__ rp_t, int* __restrict__ rp_s,
    uint8_t* __restrict__ mask,
    uint32_t a0, uint32_t b0, uint32_t a1, uint32_t b1, uint32_t a2, uint32_t b2)
{
    if (blockIdx.x >= 2) {
        // mask generation on otherwise-idle SMs
        const int RANGE = (R2 - R1) * 32;
        const int TOTAL = 3 * RANGE;
        int stride = (gridDim.x - 2) * 1024;
        for (int u = (blockIdx.x - 2) * 1024 + threadIdx.x; u < TOTAL; u += stride) {
            int layer = u / RANGE;
            int r     = R1 * 32 + (u - layer * RANGE);
            uint32_t k0, k1;
            pick_key(layer, a0, b0, a1, b1, a2, b2, &k0, &k1);
            uint32_t k2 = k0 ^ k1 ^ 0x1BD11BDAu;
            mask[layer * MASKB + r] = (uint8_t)mask8(k0, k1, k2, (uint32_t)r * 8u);
        }
        return;
    }

    const int* c  = (blockIdx.x == 0) ? cnt  : cnt + NPOI;
    int* rowptr   = (blockIdx.x == 0) ? rp_t : rp_s;
    const int n = NPOI;

    __shared__ int carry;
    __shared__ int wsum[32];
    int tid = threadIdx.x, lane = tid & 31, wid = tid >> 5;
    if (tid == 0) carry = 0;
    __syncthreads();
    for (int base = 0; base < n; base += 1024) {
        int c0 = carry;
        int i = base + tid;
        int v = (i < n) ? c[i] : 0;
        int inc = v;
        #pragma unroll
        for (int o = 1; o < 32; o <<= 1) {
            int t = __shfl_up_sync(0xFFFFFFFFu, inc, o);
            if (lane >= o) inc += t;
        }
        if (lane == 31) wsum[wid] = inc;
        __syncthreads();
        if (wid == 0) {
            int s = wsum[lane];
            #pragma unroll
            for (int o = 1; o < 32; o <<= 1) {
                int t = __shfl_up_sync(0xFFFFFFFFu, s, o);
                if (lane >= o) s += t;
            }
            wsum[lane] = s;
        }
        __syncthreads();
        int block_incl = inc + (wid ? wsum[wid - 1] : 0);
        if (i < n) rowptr[i] = c0 + block_incl - v;
        __syncthreads();
        if (tid == 1023) carry = c0 + block_incl;
        __syncthreads();
    }
    if (tid == 0) rowptr[n] = carry;
}

// --- CSR build: rank-based scatter (8B records) + mask [R2,R3)x3 ------------
__global__ void __launch_bounds__(256) scatter2_kernel(
    const int* __restrict__ tar_cols, const float* __restrict__ tar_vals,
    const int* __restrict__ src_cols, const float* __restrict__ src_vals,
    const int* __restrict__ rp_t, const int* __restrict__ rp_s,
    const uint32_t* __restrict__ rr_t, const uint32_t* __restrict__ rr_s,
    int2* __restrict__ et, int2* __restrict__ es,
    uint8_t* __restrict__ mask, int nnz,
    uint32_t a0, uint32_t b0, uint32_t a1, uint32_t b1, uint32_t a2, uint32_t b2)
{
    int t = blockIdx.x * 256 + threadIdx.x;
    if (t < nnz) {
        {
            uint32_t rr = __ldcs(rr_t + t);
            int pos = __ldg(rp_t + (rr >> 16)) + (int)(rr & 0xFFFFu);
            et[pos] = make_int2(__ldg(tar_cols + t), __float_as_int(__ldg(tar_vals + t)));
        }
        {
            uint32_t rr = __ldcs(rr_s + t);
            int pos = __ldg(rp_s + (rr >> 16)) + (int)(rr & 0xFFFFu);
            es[pos] = make_int2(__ldg(src_cols + t), __float_as_int(__ldg(src_vals + t)));
        }
    }
    const int RANGE = (R3 - R2) * 32;
    if (t < 3 * RANGE) {
        int layer = t / RANGE;
        int r     = R2 * 32 + (t - layer * RANGE);
        uint32_t k0, k1;
        pick_key(layer, a0, b0, a1, b1, a2, b2, &k0, &k1);
        uint32_t k2 = k0 ^ k1 ^ 0x1BD11BDAu;
        mask[layer * MASKB + r] = (uint8_t)mask8(k0, k1, k2, (uint32_t)r * 8u);
    }
}

// ---- SpMM inner loop macro: unroll-8 gather-accumulate ----------------------
#define SPMM_LOOP(m, edges, X, g, s, e)                                        \
    {                                                                          \
        int j = (s);                                                           \
        for (; j + 7 < (e); j += 8) {                                          \
            int2 E[8]; uint4 A[8];                                             \
            _Pragma("unroll")                                                  \
            for (int q = 0; q < 8; q++) E[q] = __ldcs((edges) + j + q);        \
            _Pragma("unroll")                                                  \
            for (int q = 0; q < 8; q++)                                        \
                A[q] = __ldg((X) + (size_t)E[q].x * D16 + (g));                \
            _Pragma("unroll")                                                  \
            for (int q = 0; q < 8; q++)                                        \
                acc8(m, __int_as_float(E[q].y), A[q]);                         \
        }                                                                      \
        for (; j < (e); j++) {                                                 \
            int2 e0 = __ldcs((edges) + j);                                     \
            uint4 a0 = __ldg((X) + (size_t)e0.x * D16 + (g));                  \
            acc8(m, __int_as_float(e0.y), a0);                                 \
        }                                                                      \
    }

// ------- tar SpMM (fp16 operand, 8B edges) + mask [R3,R4) -------------------
__global__ void __launch_bounds__(256) spmm_h(
    const int* __restrict__ rowptr, const int2* __restrict__ edges,
    const uint4* __restrict__ X, uint4* __restrict__ Y,
    uint8_t* __restrict__ maskL, uint32_t k0, uint32_t k1)
{
    int row = blockIdx.x * 8 + (threadIdx.x >> 5);
    int g   = threadIdx.x & 31;
    int s = __ldg(rowptr + row), e = __ldg(rowptr + row + 1);
    float m[8] = {0.f, 0.f, 0.f, 0.f, 0.f, 0.f, 0.f, 0.f};
    SPMM_LOOP(m, edges, X, g, s, e)
    Y[(size_t)row * D16 + g] = pack8(m);

    if (row >= R3 && row < R4) {
        uint32_t k2 = k0 ^ k1 ^ 0x1BD11BDAu;
        uint32_t r = (uint32_t)(row * 32 + g);
        maskL[r] = (uint8_t)mask8(k0, k1, k2, r * 8u);
    }
}

// --- src SpMM fused: residual + dropout + deferred-mean epilogue ------------
// mode 0: v = drop(msg+poi);   x1 = v            (residual = poi f32)
// mode 1: v = drop(msg+x1);    x2 = v            (residual = x1 fp16)
// mode 2: v = drop(msg+x2);    out = (poi + x1 + x2 + v) * 0.25
__global__ void __launch_bounds__(256) spmm_h_fused(
    const int* __restrict__ rowptr, const int2* __restrict__ edges,
    const uint4* __restrict__ X, const uint8_t* __restrict__ maskL,
    const float4* __restrict__ poi, const uint4* __restrict__ res16,
    const uint4* __restrict__ aux16, uint4* __restrict__ xout16,
    float4* __restrict__ out, uint32_t k0, uint32_t k1, int mode)
{
    int row = blockIdx.x * 8 + (threadIdx.x >> 5);
    int g   = threadIdx.x & 31;
    int s = __ldg(rowptr + row), e = __ldg(rowptr + row + 1);

    uint32_t m8;
    if (row < R4) {
        m8 = maskL[row * 32 + g];
    } else {
        uint32_t k2 = k0 ^ k1 ^ 0x1BD11BDAu;
        m8 = mask8(k0, k1, k2, (uint32_t)(row * DIM + g * 8));
    }

    float m[8] = {0.f, 0.f, 0.f, 0.f, 0.f, 0.f, 0.f, 0.f};
    SPMM_LOOP(m, edges, X, g, s, e)

    size_t i4  = (size_t)row * D4 + g * 2;
    size_t i16 = (size_t)row * D16 + g;

    float pv[8];
    if (mode == 0) {
        float4 p0 = __ldg(poi + i4), p1 = __ldg(poi + i4 + 1);
        pv[0] = p0.x; pv[1] = p0.y; pv[2] = p0.z; pv[3] = p0.w;
        pv[4] = p1.x; pv[5] = p1.y; pv[6] = p1.z; pv[7] = p1.w;
    } else {
        unpack8(pv, res16[i16]);
    }

    float v[8];
    #pragma unroll
    for (int t = 0; t < 8; t++)
        v[t] = ((m8 >> t) & 1u) ? (m[t] + pv[t]) * KEEP_INV : 0.0f;

    if (mode != 2) {
        xout16[i16] = pack8(v);
    } else {
        float4 p0 = __ldg(poi + i4), p1 = __ldg(poi + i4 + 1);
        float x1v[8];
        unpack8(x1v, aux16[i16]);
        // pv holds x2 (residual); v = v3
        out[i4] = make_float4(
            (p0.x + x1v[0] + pv[0] + v[0]) * 0.25f,
            (p0.y + x1v[1] + pv[1] + v[1]) * 0.25f,
            (p0.z + x1v[2] + pv[2] + v[2]) * 0.25f,
            (p0.w + x1v[3] + pv[3] + v[3]) * 0.25f);
        out[i4 + 1] = make_float4(
            (p1.x + x1v[4] + pv[4] + v[4]) * 0.25f,
            (p1.y + x1v[5] + pv[5] + v[5]) * 0.25f,
            (p1.z + x1v[6] + pv[6] + v[6]) * 0.25f,
            (p1.w + x1v[7] + pv[7] + v[7]) * 0.25f);
    }
}

// ---------------- host-side threefry (per-layer fold_in keys) ---------------
static inline unsigned h_rotl(unsigned x, int r) { return (x << r) | (x >> (32 - r)); }
static void host_threefry(unsigned k0, unsigned k1, unsigned x0, unsigned x1,
                          unsigned* o0, unsigned* o1)
{
    const int rots[2][4] = {{13, 15, 26, 6}, {17, 29, 16, 24}};
    unsigned ks[3] = {k0, k1, k0 ^ k1 ^ 0x1BD11BDAu};
    x0 += ks[0]; x1 += ks[1];
    for (int g = 0; g < 5; g++) {
        for (int j = 0; j < 4; j++) {
            x0 += x1; x1 = h_rotl(x1, rots[g & 1][j]); x1 ^= x0;
        }
        x0 += ks[(g + 1) % 3];
        x1 += ks[(g + 2) % 3] + (unsigned)(g + 1);
    }
    *o0 = x0; *o1 = x1;
}

extern "C" void kernel_launch(void* const* d_in, const int* in_sizes, int n_in,
                              void* d_out, int out_size)
{
    const float* poi     = (const float*)d_in[0];
    const int*   src_row = (const int*)  d_in[1];
    const int*   src_col = (const int*)  d_in[2];
    const float* src_val = (const float*)d_in[3];
    const int*   tar_row = (const int*)  d_in[4];
    const int*   tar_col = (const int*)  d_in[5];
    const float* tar_val = (const float*)d_in[6];
    int nnz = in_sizes[1];

    uint4 *p16, *x1, *x2, *mt16;
    uint8_t *mask;
    int *rp_s, *rp_t, *cnt;
    uint32_t *rr_t, *rr_s;
    int2 *es, *et;
    cudaGetSymbolAddress((void**)&p16,  g_p16);
    cudaGetSymbolAddress((void**)&x1,   g_x1);
    cudaGetSymbolAddress((void**)&x2,   g_x2);
    cudaGetSymbolAddress((void**)&mt16, g_mt16);
    cudaGetSymbolAddress((void**)&mask, g_mask);
    cudaGetSymbolAddress((void**)&rp_s, g_rp_src);
    cudaGetSymbolAddress((void**)&rp_t, g_rp_tar);
    cudaGetSymbolAddress((void**)&cnt,  g_cnt);
    cudaGetSymbolAddress((void**)&rr_t, g_rr_t);
    cudaGetSymbolAddress((void**)&rr_s, g_rr_s);
    cudaGetSymbolAddress((void**)&es,   g_e_src);
    cudaGetSymbolAddress((void**)&et,   g_e_tar);

    unsigned lk0[3], lk1[3];
    for (unsigned i = 0; i < 3; i++)
        host_threefry(0u, 42u, 0u, i, &lk0[i], &lk1[i]);

    int nthreads = nnz > NPOI * D16 ? nnz : NPOI * D16;
    int eb = (nthreads + 255) / 256;
    int rb = NPOI / 8;

    // ---- fused CSR build (+ fp16 snapshot + mask rows [0,R3) x 3 layers) ---
    cudaMemsetAsync(cnt, 0, 2 * NPOI * sizeof(int), 0);
    hist2_kernel<<<eb, 256>>>(tar_row, src_row, cnt, rr_t, rr_s,
                              (const float4*)poi, p16, mask, nnz,
                              lk0[0], lk1[0], lk0[1], lk1[1], lk0[2], lk1[2]);
    scan2_kernel<<<148, 1024>>>(cnt, rp_t, rp_s, mask,
                                lk0[0], lk1[0], lk0[1], lk1[1], lk0[2], lk1[2]);
    scatter2_kernel<<<eb, 256>>>(tar_col, tar_val, src_col, src_val,
                                 rp_t, rp_s, rr_t, rr_s, et, es, mask, nnz,
                                 lk0[0], lk1[0], lk0[1], lk1[1], lk0[2], lk1[2]);

    // ---- 3 layers (deferred mean; x_i kept in fp16 buffers) ----
    const uint4* gx[3]  = {p16, x1, x2};
    uint4*       xo[3]  = {x1, x2, nullptr};
    const uint4* res[3] = {nullptr, x1, x2};
    for (int i = 0; i < 3; i++) {
        uint8_t* maskL = mask + (size_t)i * MASKB;
        spmm_h<<<rb, 256>>>(rp_t, et, gx[i], mt16, maskL, lk0[i], lk1[i]);
        spmm_h_fused<<<rb, 256>>>(rp_s, es, mt16, maskL,
                                  (const float4*)poi, res[i], x1,
                                  xo[i], (float4*)d_out,
                                  lk0[i], lk1[i], i);
    }
}

// round 10
// speedup vs baseline: 1.0474x; 1.0129x over previous
#include <cuda_runtime.h>
#include <cuda_fp16.h>
#include <stdint.h>

// Problem constants (fixed by setup_inputs)
#define NPOI    50000
#define DIM     256
#define D4      (DIM / 4)            // 64 float4 per row (fp32)
#define D16     (DIM / 8)            // 32 uint4 per row (fp16)
#define NELEM   (NPOI * DIM)
#define NV4     (NELEM / 4)
#define NNZ_MAX 1600000
#define MASKB   (NELEM / 8)          // mask bytes per layer (1.6M)
#define THRESH  0xE6666600u          // bits < THRESH <=> uniform(bits) < 0.9f
#define KEEP_INV (1.0f / 0.9f)
// mask-generation row ranges (who computes which rows' dropout masks)
#define R1      9216                 // [0,R1)    x3 -> hist2
#define R2      17408                // [R1,R2)   x3 -> scan2 idle blocks
#define R3      29696                // [R2,R3)   x3 -> scatter2
#define R4      40960                // [R3,R4)   per layer -> spmm_h
                                     // [R4,NPOI) per layer -> fused inline

// ---------------- scratch (static device globals) ---------------------------
__device__ uint4    g_p16[NPOI * D16];   // poi in fp16 (layer-0 gather)
__device__ uint4    g_x1[NPOI * D16];    // x_1 fp16
__device__ uint4    g_x2[NPOI * D16];    // x_2 fp16
__device__ uint4    g_mt16[NPOI * D16];  // msg_tar fp16
__device__ uint8_t  g_mask[3 * MASKB];   // dropout mask bits, 3 layers
__device__ int      g_rp_src[NPOI + 1], g_rp_tar[NPOI + 1];
__device__ int      g_cnt[2 * NPOI];
__device__ uint32_t g_rr_t[NNZ_MAX], g_rr_s[NNZ_MAX];  // (row<<16)|rank
__device__ int2     g_e_src[NNZ_MAX], g_e_tar[NNZ_MAX]; // (col, val-bits f32)

// ---------------- fp16 helpers ----------------------------------------------
__device__ __forceinline__ void acc8(float* a, float v, uint4 q)
{
    float2 f;
    f = __half22float2(*(__half2*)&q.x); a[0] = fmaf(v, f.x, a[0]); a[1] = fmaf(v, f.y, a[1]);
    f = __half22float2(*(__half2*)&q.y); a[2] = fmaf(v, f.x, a[2]); a[3] = fmaf(v, f.y, a[3]);
    f = __half22float2(*(__half2*)&q.z); a[4] = fmaf(v, f.x, a[4]); a[5] = fmaf(v, f.y, a[5]);
    f = __half22float2(*(__half2*)&q.w); a[6] = fmaf(v, f.x, a[6]); a[7] = fmaf(v, f.y, a[7]);
}

__device__ __forceinline__ void unpack8(float* f, uint4 q)
{
    float2 t;
    t = __half22float2(*(__half2*)&q.x); f[0] = t.x; f[1] = t.y;
    t = __half22float2(*(__half2*)&q.y); f[2] = t.x; f[3] = t.y;
    t = __half22float2(*(__half2*)&q.z); f[4] = t.x; f[5] = t.y;
    t = __half22float2(*(__half2*)&q.w); f[6] = t.x; f[7] = t.y;
}

__device__ __forceinline__ uint4 pack8(const float* a)
{
    uint4 o;
    __half2 h;
    h = __floats2half2_rn(a[0], a[1]); o.x = *(uint32_t*)&h;
    h = __floats2half2_rn(a[2], a[3]); o.y = *(uint32_t*)&h;
    h = __floats2half2_rn(a[4], a[5]); o.z = *(uint32_t*)&h;
    h = __floats2half2_rn(a[6], a[7]); o.w = *(uint32_t*)&h;
    return o;
}

// ---------------- Threefry-2x32 (JAX partitionable random_bits) -------------
__device__ __forceinline__ uint32_t tf_bits(uint32_t k0, uint32_t k1,
                                            uint32_t k2, uint32_t ctr)
{
    uint32_t x0 = k0;
    uint32_t x1 = ctr + k1;
#define TFR(r) { x0 += x1; x1 = __funnelshift_l(x1, x1, (r)); x1 ^= x0; }
    TFR(13) TFR(15) TFR(26) TFR(6)    x0 += k1; x1 += k2 + 1u;
    TFR(17) TFR(29) TFR(16) TFR(24)   x0 += k2; x1 += k0 + 2u;
    TFR(13) TFR(15) TFR(26) TFR(6)    x0 += k0; x1 += k1 + 3u;
    TFR(17) TFR(29) TFR(16) TFR(24)   x0 += k1; x1 += k2 + 4u;
    TFR(13) TFR(15) TFR(26) TFR(6)    x0 += k2; x1 += k0 + 5u;
#undef TFR
    return x0 ^ x1;
}

__device__ __forceinline__ uint32_t mask8(uint32_t k0, uint32_t k1,
                                          uint32_t k2, uint32_t base)
{
    uint32_t m = 0;
    #pragma unroll
    for (int t = 0; t < 8; t++)
        m |= (tf_bits(k0, k1, k2, base + (uint32_t)t) < THRESH) ? (1u << t) : 0u;
    return m;
}

__device__ __forceinline__ void pick_key(int layer,
    uint32_t a0, uint32_t b0, uint32_t a1, uint32_t b1,
    uint32_t a2, uint32_t b2, uint32_t* k0, uint32_t* k1)
{
    *k0 = (layer == 0) ? a0 : (layer == 1) ? a1 : a2;
    *k1 = (layer == 0) ? b0 : (layer == 1) ? b1 : b2;
}

// -- CSR build: histogram (packed rank) + fp16 convert + mask [0,R1)x3 -------
__global__ void __launch_bounds__(256) hist2_kernel(
    const int* __restrict__ tar_rows, const int* __restrict__ src_rows,
    int* __restrict__ cnt, uint32_t* __restrict__ rr_t, uint32_t* __restrict__ rr_s,
    const float4* __restrict__ poi, uint4* __restrict__ p16,
    uint8_t* __restrict__ mask, int nnz,
    uint32_t a0, uint32_t b0, uint32_t a1, uint32_t b1, uint32_t a2, uint32_t b2)
{
    int t = blockIdx.x * 256 + threadIdx.x;
    if (t < nnz) {
        int rt_row = __ldg(tar_rows + t);
        int rs_row = __ldg(src_rows + t);
        int rt = atomicAdd(cnt + rt_row, 1);
        int rs = atomicAdd(cnt + NPOI + rs_row, 1);
        __stcs(rr_t + t, ((uint32_t)rt_row << 16) | (uint32_t)rt);
        __stcs(rr_s + t, ((uint32_t)rs_row << 16) | (uint32_t)rs);
    }
    if (t < NPOI * D16) {
        float4 a = __ldg(poi + t * 2), b = __ldg(poi + t * 2 + 1);
        float v[8] = {a.x, a.y, a.z, a.w, b.x, b.y, b.z, b.w};
        p16[t] = pack8(v);
    }
    if (t < 3 * R1 * 32) {
        int layer = t / (R1 * 32);
        int r     = t - layer * (R1 * 32);
        uint32_t k0, k1;
        pick_key(layer, a0, b0, a1, b1, a2, b2, &k0, &k1);
        uint32_t k2 = k0 ^ k1 ^ 0x1BD11BDAu;
        mask[layer * MASKB + r] = (uint8_t)mask8(k0, k1, k2, (uint32_t)r * 8u);
    }
}

// --- CSR build: 2-block exclusive scan; blocks >=2 generate mask [R1,R2)x3 --
__global__ void __launch_bounds__(1024) scan2_kernel(
    const int* __restrict__ cnt, int* __restrict__ rp_t, int* __restrict__ rp_s,
    uint8_t* __restrict__ mask,
    uint32_t a0, uint32_t b0, uint32_t a1, uint32_t b1, uint32_t a2, uint32_t b2)
{
    if (blockIdx.x >= 2) {
        const int RANGE = (R2 - R1) * 32;
        const int TOTAL = 3 * RANGE;
        int stride = (gridDim.x - 2) * 1024;
        for (int u = (blockIdx.x - 2) * 1024 + threadIdx.x; u < TOTAL; u += stride) {
            int layer = u / RANGE;
            int r     = R1 * 32 + (u - layer * RANGE);
            uint32_t k0, k1;
            pick_key(layer, a0, b0, a1, b1, a2, b2, &k0, &k1);
            uint32_t k2 = k0 ^ k1 ^ 0x1BD11BDAu;
            mask[layer * MASKB + r] = (uint8_t)mask8(k0, k1, k2, (uint32_t)r * 8u);
        }
        return;
    }

    const int* c  = (blockIdx.x == 0) ? cnt  : cnt + NPOI;
    int* rowptr   = (blockIdx.x == 0) ? rp_t : rp_s;
    const int n = NPOI;

    __shared__ int carry;
    __shared__ int wsum[32];
    int tid = threadIdx.x, lane = tid & 31, wid = tid >> 5;
    if (tid == 0) carry = 0;
    __syncthreads();
    for (int base = 0; base < n; base += 1024) {
        int c0 = carry;
        int i = base + tid;
        int v = (i < n) ? c[i] : 0;
        int inc = v;
        #pragma unroll
        for (int o = 1; o < 32; o <<= 1) {
            int t = __shfl_up_sync(0xFFFFFFFFu, inc, o);
            if (lane >= o) inc += t;
        }
        if (lane == 31) wsum[wid] = inc;
        __syncthreads();
        if (wid == 0) {
            int s = wsum[lane];
            #pragma unroll
            for (int o = 1; o < 32; o <<= 1) {
                int t = __shfl_up_sync(0xFFFFFFFFu, s, o);
                if (lane >= o) s += t;
            }
            wsum[lane] = s;
        }
        __syncthreads();
        int block_incl = inc + (wid ? wsum[wid - 1] : 0);
        if (i < n) rowptr[i] = c0 + block_incl - v;
        __syncthreads();
        if (tid == 1023) carry = c0 + block_incl;
        __syncthreads();
    }
    if (tid == 0) rowptr[n] = carry;
}

// --- CSR build: rank-based scatter (8B records) + mask [R2,R3)x3 ------------
__global__ void __launch_bounds__(256) scatter2_kernel(
    const int* __restrict__ tar_cols, const float* __restrict__ tar_vals,
    const int* __restrict__ src_cols, const float* __restrict__ src_vals,
    const int* __restrict__ rp_t, const int* __restrict__ rp_s,
    const uint32_t* __restrict__ rr_t, const uint32_t* __restrict__ rr_s,
    int2* __restrict__ et, int2* __restrict__ es,
    uint8_t* __restrict__ mask, int nnz,
    uint32_t a0, uint32_t b0, uint32_t a1, uint32_t b1, uint32_t a2, uint32_t b2)
{
    int t = blockIdx.x * 256 + threadIdx.x;
    if (t < nnz) {
        {
            uint32_t rr = __ldcs(rr_t + t);
            int pos = __ldg(rp_t + (rr >> 16)) + (int)(rr & 0xFFFFu);
            et[pos] = make_int2(__ldg(tar_cols + t), __float_as_int(__ldg(tar_vals + t)));
        }
        {
            uint32_t rr = __ldcs(rr_s + t);
            int pos = __ldg(rp_s + (rr >> 16)) + (int)(rr & 0xFFFFu);
            es[pos] = make_int2(__ldg(src_cols + t), __float_as_int(__ldg(src_vals + t)));
        }
    }
    const int RANGE = (R3 - R2) * 32;
    if (t < 3 * RANGE) {
        int layer = t / RANGE;
        int r     = R2 * 32 + (t - layer * RANGE);
        uint32_t k0, k1;
        pick_key(layer, a0, b0, a1, b1, a2, b2, &k0, &k1);
        uint32_t k2 = k0 ^ k1 ^ 0x1BD11BDAu;
        mask[layer * MASKB + r] = (uint8_t)mask8(k0, k1, k2, (uint32_t)r * 8u);
    }
}

// ---- SpMM inner loop: unroll-8, paired (int4) edge loads --------------------
// (edges+j) is 16B-aligned when j is even (array base is 256B-aligned)
#define SPMM_LOOP(m, edges, X, g, s, e)                                        \
    {                                                                          \
        int j = (s);                                                           \
        if ((j & 1) && j < (e)) {                                              \
            int2 e0 = __ldcs((edges) + j);                                     \
            uint4 a0 = __ldg((X) + (size_t)e0.x * D16 + (g));                  \
            acc8(m, __int_as_float(e0.y), a0);                                 \
            j++;                                                               \
        }                                                                      \
        for (; j + 7 < (e); j += 8) {                                          \
            int4 P[4]; uint4 A[8];                                             \
            const int4* ep = (const int4*)((edges) + j);                       \
            _Pragma("unroll")                                                  \
            for (int q = 0; q < 4; q++) P[q] = __ldcs(ep + q);                 \
            _Pragma("unroll")                                                  \
            for (int q = 0; q < 4; q++) {                                      \
                A[2 * q]     = __ldg((X) + (size_t)P[q].x * D16 + (g));        \
                A[2 * q + 1] = __ldg((X) + (size_t)P[q].z * D16 + (g));        \
            }                                                                  \
            _Pragma("unroll")                                                  \
            for (int q = 0; q < 4; q++) {                                      \
                acc8(m, __int_as_float(P[q].y), A[2 * q]);                     \
                acc8(m, __int_as_float(P[q].w), A[2 * q + 1]);                 \
            }                                                                  \
        }                                                                      \
        for (; j < (e); j++) {                                                 \
            int2 e0 = __ldcs((edges) + j);                                     \
            uint4 a0 = __ldg((X) + (size_t)e0.x * D16 + (g));                  \
            acc8(m, __int_as_float(e0.y), a0);                                 \
        }                                                                      \
    }

// ------- tar SpMM (fp16 operand, 8B edges) + mask [R3,R4) -------------------
__global__ void __launch_bounds__(256, 4) spmm_h(
    const int* __restrict__ rowptr, const int2* __restrict__ edges,
    const uint4* __restrict__ X, uint4* __restrict__ Y,
    uint8_t* __restrict__ maskL, uint32_t k0, uint32_t k1)
{
    int row = blockIdx.x * 8 + (threadIdx.x >> 5);
    int g   = threadIdx.x & 31;
    int s = __ldg(rowptr + row), e = __ldg(rowptr + row + 1);
    float m[8] = {0.f, 0.f, 0.f, 0.f, 0.f, 0.f, 0.f, 0.f};
    SPMM_LOOP(m, edges, X, g, s, e)
    Y[(size_t)row * D16 + g] = pack8(m);

    if (row >= R3 && row < R4) {
        uint32_t k2 = k0 ^ k1 ^ 0x1BD11BDAu;
        uint32_t r = (uint32_t)(row * 32 + g);
        maskL[r] = (uint8_t)mask8(k0, k1, k2, r * 8u);
    }
}

// --- src SpMM fused: residual + dropout + deferred-mean epilogue ------------
// mode 0: v = drop(msg+poi);   x1 = v            (residual = poi f32)
// mode 1: v = drop(msg+x1);    x2 = v            (residual = x1 fp16)
// mode 2: v = drop(msg+x2);    out = (poi + x1 + x2 + v) * 0.25
__global__ void __launch_bounds__(256, 4) spmm_h_fused(
    const int* __restrict__ rowptr, const int2* __restrict__ edges,
    const uint4* __restrict__ X, const uint8_t* __restrict__ maskL,
    const float4* __restrict__ poi, const uint4* __restrict__ res16,
    const uint4* __restrict__ aux16, uint4* __restrict__ xout16,
    float4* __restrict__ out, uint32_t k0, uint32_t k1, int mode)
{
    int row = blockIdx.x * 8 + (threadIdx.x >> 5);
    int g   = threadIdx.x & 31;
    int s = __ldg(rowptr + row), e = __ldg(rowptr + row + 1);

    uint32_t m8;
    if (row < R4) {
        m8 = maskL[row * 32 + g];
    } else {
        uint32_t k2 = k0 ^ k1 ^ 0x1BD11BDAu;
        m8 = mask8(k0, k1, k2, (uint32_t)(row * DIM + g * 8));
    }

    float m[8] = {0.f, 0.f, 0.f, 0.f, 0.f, 0.f, 0.f, 0.f};
    SPMM_LOOP(m, edges, X, g, s, e)

    size_t i4  = (size_t)row * D4 + g * 2;
    size_t i16 = (size_t)row * D16 + g;

    float pv[8];
    if (mode == 0) {
        float4 p0 = __ldg(poi + i4), p1 = __ldg(poi + i4 + 1);
        pv[0] = p0.x; pv[1] = p0.y; pv[2] = p0.z; pv[3] = p0.w;
        pv[4] = p1.x; pv[5] = p1.y; pv[6] = p1.z; pv[7] = p1.w;
    } else {
        unpack8(pv, res16[i16]);
    }

    float v[8];
    #pragma unroll
    for (int t = 0; t < 8; t++)
        v[t] = ((m8 >> t) & 1u) ? (m[t] + pv[t]) * KEEP_INV : 0.0f;

    if (mode != 2) {
        xout16[i16] = pack8(v);
    } else {
        float4 p0 = __ldg(poi + i4), p1 = __ldg(poi + i4 + 1);
        float x1v[8];
        unpack8(x1v, aux16[i16]);
        // pv holds x2 (residual); v = v3
        out[i4] = make_float4(
            (p0.x + x1v[0] + pv[0] + v[0]) * 0.25f,
            (p0.y + x1v[1] + pv[1] + v[1]) * 0.25f,
            (p0.z + x1v[2] + pv[2] + v[2]) * 0.25f,
            (p0.w + x1v[3] + pv[3] + v[3]) * 0.25f);
        out[i4 + 1] = make_float4(
            (p1.x + x1v[4] + pv[4] + v[4]) * 0.25f,
            (p1.y + x1v[5] + pv[5] + v[5]) * 0.25f,
            (p1.z + x1v[6] + pv[6] + v[6]) * 0.25f,
            (p1.w + x1v[7] + pv[7] + v[7]) * 0.25f);
    }
}

// ---------------- host-side threefry (per-layer fold_in keys) ---------------
static inline unsigned h_rotl(unsigned x, int r) { return (x << r) | (x >> (32 - r)); }
static void host_threefry(unsigned k0, unsigned k1, unsigned x0, unsigned x1,
                          unsigned* o0, unsigned* o1)
{
    const int rots[2][4] = {{13, 15, 26, 6}, {17, 29, 16, 24}};
    unsigned ks[3] = {k0, k1, k0 ^ k1 ^ 0x1BD11BDAu};
    x0 += ks[0]; x1 += ks[1];
    for (int g = 0; g < 5; g++) {
        for (int j = 0; j < 4; j++) {
            x0 += x1; x1 = h_rotl(x1, rots[g & 1][j]); x1 ^= x0;
        }
        x0 += ks[(g + 1) % 3];
        x1 += ks[(g + 2) % 3] + (unsigned)(g + 1);
    }
    *o0 = x0; *o1 = x1;
}

extern "C" void kernel_launch(void* const* d_in, const int* in_sizes, int n_in,
                              void* d_out, int out_size)
{
    const float* poi     = (const float*)d_in[0];
    const int*   src_row = (const int*)  d_in[1];
    const int*   src_col = (const int*)  d_in[2];
    const float* src_val = (const float*)d_in[3];
    const int*   tar_row = (const int*)  d_in[4];
    const int*   tar_col = (const int*)  d_in[5];
    const float* tar_val = (const float*)d_in[6];
    int nnz = in_sizes[1];

    uint4 *p16, *x1, *x2, *mt16;
    uint8_t *mask;
    int *rp_s, *rp_t, *cnt;
    uint32_t *rr_t, *rr_s;
    int2 *es, *et;
    cudaGetSymbolAddress((void**)&p16,  g_p16);
    cudaGetSymbolAddress((void**)&x1,   g_x1);
    cudaGetSymbolAddress((void**)&x2,   g_x2);
    cudaGetSymbolAddress((void**)&mt16, g_mt16);
    cudaGetSymbolAddress((void**)&mask, g_mask);
    cudaGetSymbolAddress((void**)&rp_s, g_rp_src);
    cudaGetSymbolAddress((void**)&rp_t, g_rp_tar);
    cudaGetSymbolAddress((void**)&cnt,  g_cnt);
    cudaGetSymbolAddress((void**)&rr_t, g_rr_t);
    cudaGetSymbolAddress((void**)&rr_s, g_rr_s);
    cudaGetSymbolAddress((void**)&es,   g_e_src);
    cudaGetSymbolAddress((void**)&et,   g_e_tar);

    unsigned lk0[3], lk1[3];
    for (unsigned i = 0; i < 3; i++)
        host_threefry(0u, 42u, 0u, i, &lk0[i], &lk1[i]);

    int nthreads = nnz > NPOI * D16 ? nnz : NPOI * D16;
    int eb = (nthreads + 255) / 256;
    int rb = NPOI / 8;

    // ---- fused CSR build (+ fp16 snapshot + mask rows [0,R3) x 3 layers) ---
    cudaMemsetAsync(cnt, 0, 2 * NPOI * sizeof(int), 0);
    hist2_kernel<<<eb, 256>>>(tar_row, src_row, cnt, rr_t, rr_s,
                              (const float4*)poi, p16, mask, nnz,
                              lk0[0], lk1[0], lk0[1], lk1[1], lk0[2], lk1[2]);
    scan2_kernel<<<148, 1024>>>(cnt, rp_t, rp_s, mask,
                                lk0[0], lk1[0], lk0[1], lk1[1], lk0[2], lk1[2]);
    scatter2_kernel<<<eb, 256>>>(tar_col, tar_val, src_col, src_val,
                                 rp_t, rp_s, rr_t, rr_s, et, es, mask, nnz,
                                 lk0[0], lk1[0], lk0[1], lk1[1], lk0[2], lk1[2]);

    // ---- 3 layers (deferred mean; x_i kept in fp16 buffers) ----
    const uint4* gx[3]  = {p16, x1, x2};
    uint4*       xo[3]  = {x1, x2, nullptr};
    const uint4* res[3] = {nullptr, x1, x2};
    for (int i = 0; i < 3; i++) {
        uint8_t* maskL = mask + (size_t)i * MASKB;
        spmm_h<<<rb, 256>>>(rp_t, et, gx[i], mt16, maskL, lk0[i], lk1[i]);
        spmm_h_fused<<<rb, 256>>>(rp_s, es, mt16, maskL,
                                  (const float4*)poi, res[i], x1,
                                  xo[i], (float4*)d_out,
                                  lk0[i], lk1[i], i);
    }
}

// round 11
// speedup vs baseline: 1.0930x; 1.0436x over previous
#include <cuda_runtime.h>
#include <cuda_fp16.h>
#include <stdint.h>

// Problem constants (fixed by setup_inputs)
#define NPOI    50000
#define DIM     256
#define D4      (DIM / 4)            // 64 float4 per row (fp32)
#define D16     (DIM / 8)            // 32 uint4 per row (fp16)
#define NELEM   (NPOI * DIM)
#define NV4     (NELEM / 4)
#define NNZ_MAX 1600000
#define MASKB   (NELEM / 8)          // mask bytes per layer (1.6M)
#define THRESH  0xE6666600u          // bits < THRESH <=> uniform(bits) < 0.9f
#define KEEP_INV (1.0f / 0.9f)
// mask-generation row ranges (who computes which rows' dropout masks)
#define R1      9216                 // [0,R1)    x3 -> hist2
#define R2      17408                // [R1,R2)   x3 -> scan2 idle blocks
#define R3      29696                // [R2,R3)   x3 -> scatter_tar
#define R4      40960                // [R3,R4)   per layer -> spmm_h
                                     // [R4,NPOI) per layer -> fused inline
#define RB      (NPOI / 8)           // 6250 spmm row-blocks

// ---------------- scratch (static device globals) ---------------------------
__device__ uint4    g_x16[NPOI * D16];   // x_i fp16 (gather + residual, in-place)
__device__ uint4    g_mt16[NPOI * D16];  // msg_tar fp16
__device__ float4   g_acc[NV4];          // running sum of finals (fp32)
__device__ uint8_t  g_mask[3 * MASKB];   // dropout mask bits, 3 layers
__device__ int      g_rp_src[NPOI + 1], g_rp_tar[NPOI + 1];
__device__ int      g_cnt[2 * NPOI];
__device__ uint32_t g_rr_t[NNZ_MAX], g_rr_s[NNZ_MAX];  // (row<<16)|rank
__device__ int2     g_e_src[NNZ_MAX], g_e_tar[NNZ_MAX]; // (col, val-bits f32)

// ---------------- fp16 helpers ----------------------------------------------
__device__ __forceinline__ void acc8(float* a, float v, uint4 q)
{
    float2 f;
    f = __half22float2(*(__half2*)&q.x); a[0] = fmaf(v, f.x, a[0]); a[1] = fmaf(v, f.y, a[1]);
    f = __half22float2(*(__half2*)&q.y); a[2] = fmaf(v, f.x, a[2]); a[3] = fmaf(v, f.y, a[3]);
    f = __half22float2(*(__half2*)&q.z); a[4] = fmaf(v, f.x, a[4]); a[5] = fmaf(v, f.y, a[5]);
    f = __half22float2(*(__half2*)&q.w); a[6] = fmaf(v, f.x, a[6]); a[7] = fmaf(v, f.y, a[7]);
}

__device__ __forceinline__ void unpack8(float* f, uint4 q)
{
    float2 t;
    t = __half22float2(*(__half2*)&q.x); f[0] = t.x; f[1] = t.y;
    t = __half22float2(*(__half2*)&q.y); f[2] = t.x; f[3] = t.y;
    t = __half22float2(*(__half2*)&q.z); f[4] = t.x; f[5] = t.y;
    t = __half22float2(*(__half2*)&q.w); f[6] = t.x; f[7] = t.y;
}

__device__ __forceinline__ uint4 pack8(const float* a)
{
    uint4 o;
    __half2 h;
    h = __floats2half2_rn(a[0], a[1]); o.x = *(uint32_t*)&h;
    h = __floats2half2_rn(a[2], a[3]); o.y = *(uint32_t*)&h;
    h = __floats2half2_rn(a[4], a[5]); o.z = *(uint32_t*)&h;
    h = __floats2half2_rn(a[6], a[7]); o.w = *(uint32_t*)&h;
    return o;
}

// ---------------- Threefry-2x32 (JAX partitionable random_bits) -------------
__device__ __forceinline__ uint32_t tf_bits(uint32_t k0, uint32_t k1,
                                            uint32_t k2, uint32_t ctr)
{
    uint32_t x0 = k0;
    uint32_t x1 = ctr + k1;
#define TFR(r) { x0 += x1; x1 = __funnelshift_l(x1, x1, (r)); x1 ^= x0; }
    TFR(13) TFR(15) TFR(26) TFR(6)    x0 += k1; x1 += k2 + 1u;
    TFR(17) TFR(29) TFR(16) TFR(24)   x0 += k2; x1 += k0 + 2u;
    TFR(13) TFR(15) TFR(26) TFR(6)    x0 += k0; x1 += k1 + 3u;
    TFR(17) TFR(29) TFR(16) TFR(24)   x0 += k1; x1 += k2 + 4u;
    TFR(13) TFR(15) TFR(26) TFR(6)    x0 += k2; x1 += k0 + 5u;
#undef TFR
    return x0 ^ x1;
}

__device__ __forceinline__ uint32_t mask8(uint32_t k0, uint32_t k1,
                                          uint32_t k2, uint32_t base)
{
    uint32_t m = 0;
    #pragma unroll
    for (int t = 0; t < 8; t++)
        m |= (tf_bits(k0, k1, k2, base + (uint32_t)t) < THRESH) ? (1u << t) : 0u;
    return m;
}

__device__ __forceinline__ void pick_key(int layer,
    uint32_t a0, uint32_t b0, uint32_t a1, uint32_t b1,
    uint32_t a2, uint32_t b2, uint32_t* k0, uint32_t* k1)
{
    *k0 = (layer == 0) ? a0 : (layer == 1) ? a1 : a2;
    *k1 = (layer == 0) ? b0 : (layer == 1) ? b1 : b2;
}

// -- CSR build: histogram (packed rank) + fp16 convert + mask [0,R1)x3 -------
__global__ void __launch_bounds__(256) hist2_kernel(
    const int* __restrict__ tar_rows, const int* __restrict__ src_rows,
    int* __restrict__ cnt, uint32_t* __restrict__ rr_t, uint32_t* __restrict__ rr_s,
    const float4* __restrict__ poi, uint4* __restrict__ x16,
    uint8_t* __restrict__ mask, int nnz,
    uint32_t a0, uint32_t b0, uint32_t a1, uint32_t b1, uint32_t a2, uint32_t b2)
{
    int t = blockIdx.x * 256 + threadIdx.x;
    if (t < nnz) {
        int rt_row = __ldg(tar_rows + t);
        int rs_row = __ldg(src_rows + t);
        int rt = atomicAdd(cnt + rt_row, 1);
        int rs = atomicAdd(cnt + NPOI + rs_row, 1);
        __stcs(rr_t + t, ((uint32_t)rt_row << 16) | (uint32_t)rt);
        __stcs(rr_s + t, ((uint32_t)rs_row << 16) | (uint32_t)rs);
    }
    if (t < NPOI * D16) {
        float4 a = __ldg(poi + t * 2), b = __ldg(poi + t * 2 + 1);
        float v[8] = {a.x, a.y, a.z, a.w, b.x, b.y, b.z, b.w};
        x16[t] = pack8(v);
    }
    if (t < 3 * R1 * 32) {
        int layer = t / (R1 * 32);
        int r     = t - layer * (R1 * 32);
        uint32_t k0, k1;
        pick_key(layer, a0, b0, a1, b1, a2, b2, &k0, &k1);
        uint32_t k2 = k0 ^ k1 ^ 0x1BD11BDAu;
        mask[layer * MASKB + r] = (uint8_t)mask8(k0, k1, k2, (uint32_t)r * 8u);
    }
}

// --- CSR build: 2-block exclusive scan; blocks >=2 generate mask [R1,R2)x3 --
__global__ void __launch_bounds__(1024) scan2_kernel(
    const int* __restrict__ cnt, int* __restrict__ rp_t, int* __restrict__ rp_s,
    uint8_t* __restrict__ mask,
    uint32_t a0, uint32_t b0, uint32_t a1, uint32_t b1, uint32_t a2, uint32_t b2)
{
    if (blockIdx.x >= 2) {
        const int RANGE = (R2 - R1) * 32;
        const int TOTAL = 3 * RANGE;
        int stride = (gridDim.x - 2) * 1024;
        for (int u = (blockIdx.x - 2) * 1024 + threadIdx.x; u < TOTAL; u += stride) {
            int layer = u / RANGE;
            int r     = R1 * 32 + (u - layer * RANGE);
            uint32_t k0, k1;
            pick_key(layer, a0, b0, a1, b1, a2, b2, &k0, &k1);
            uint32_t k2 = k0 ^ k1 ^ 0x1BD11BDAu;
            mask[layer * MASKB + r] = (uint8_t)mask8(k0, k1, k2, (uint32_t)r * 8u);
        }
        return;
    }

    const int* c  = (blockIdx.x == 0) ? cnt  : cnt + NPOI;
    int* rowptr   = (blockIdx.x == 0) ? rp_t : rp_s;
    const int n = NPOI;

    __shared__ int carry;
    __shared__ int wsum[32];
    int tid = threadIdx.x, lane = tid & 31, wid = tid >> 5;
    if (tid == 0) carry = 0;
    __syncthreads();
    for (int base = 0; base < n; base += 1024) {
        int c0 = carry;
        int i = base + tid;
        int v = (i < n) ? c[i] : 0;
        int inc = v;
        #pragma unroll
        for (int o = 1; o < 32; o <<= 1) {
            int t = __shfl_up_sync(0xFFFFFFFFu, inc, o);
            if (lane >= o) inc += t;
        }
        if (lane == 31) wsum[wid] = inc;
        __syncthreads();
        if (wid == 0) {
            int s = wsum[lane];
            #pragma unroll
            for (int o = 1; o < 32; o <<= 1) {
                int t = __shfl_up_sync(0xFFFFFFFFu, s, o);
                if (lane >= o) s += t;
            }
            wsum[lane] = s;
        }
        __syncthreads();
        int block_incl = inc + (wid ? wsum[wid - 1] : 0);
        if (i < n) rowptr[i] = c0 + block_incl - v;
        __syncthreads();
        if (tid == 1023) carry = c0 + block_incl;
        __syncthreads();
    }
    if (tid == 0) rowptr[n] = carry;
}

// --- CSR build: tar-side rank scatter + mask [R2,R3)x3 ----------------------
__global__ void __launch_bounds__(256) scatter_tar_kernel(
    const int* __restrict__ tar_cols, const float* __restrict__ tar_vals,
    const int* __restrict__ rp_t, const uint32_t* __restrict__ rr_t,
    int2* __restrict__ et, uint8_t* __restrict__ mask, int nnz,
    uint32_t a0, uint32_t b0, uint32_t a1, uint32_t b1, uint32_t a2, uint32_t b2)
{
    int t = blockIdx.x * 256 + threadIdx.x;
    if (t < nnz) {
        uint32_t rr = __ldcs(rr_t + t);
        int pos = __ldg(rp_t + (rr >> 16)) + (int)(rr & 0xFFFFu);
        et[pos] = make_int2(__ldg(tar_cols + t), __float_as_int(__ldg(tar_vals + t)));
    }
    const int RANGE = (R3 - R2) * 32;
    if (t < 3 * RANGE) {
        int layer = t / RANGE;
        int r     = R2 * 32 + (t - layer * RANGE);
        uint32_t k0, k1;
        pick_key(layer, a0, b0, a1, b1, a2, b2, &k0, &k1);
        uint32_t k2 = k0 ^ k1 ^ 0x1BD11BDAu;
        mask[layer * MASKB + r] = (uint8_t)mask8(k0, k1, k2, (uint32_t)r * 8u);
    }
}

// ---- SpMM inner loop macro: unroll-8 gather-accumulate (R9 config) ----------
#define SPMM_LOOP(m, edges, X, g, s, e)                                        \
    {                                                                          \
        int j = (s);                                                           \
        for (; j + 7 < (e); j += 8) {                                          \
            int2 E[8]; uint4 A[8];                                             \
            _Pragma("unroll")                                                  \
            for (int q = 0; q < 8; q++) E[q] = __ldcs((edges) + j + q);        \
            _Pragma("unroll")                                                  \
            for (int q = 0; q < 8; q++)                                        \
                A[q] = __ldg((X) + (size_t)E[q].x * D16 + (g));                \
            _Pragma("unroll")                                                  \
            for (int q = 0; q < 8; q++)                                        \
                acc8(m, __int_as_float(E[q].y), A[q]);                         \
        }                                                                      \
        for (; j < (e); j++) {                                                 \
            int2 e0 = __ldcs((edges) + j);                                     \
            uint4 a0 = __ldg((X) + (size_t)e0.x * D16 + (g));                  \
            acc8(m, __int_as_float(e0.y), a0);                                 \
        }                                                                      \
    }

// ---- spmm_h body (warp per row) ---------------------------------------------
__device__ __forceinline__ void spmm_body(
    int row, int g, const int* rowptr, const int2* edges,
    const uint4* X, uint4* Y, uint8_t* maskL, uint32_t k0, uint32_t k1)
{
    int s = __ldg(rowptr + row), e = __ldg(rowptr + row + 1);
    float m[8] = {0.f, 0.f, 0.f, 0.f, 0.f, 0.f, 0.f, 0.f};
    SPMM_LOOP(m, edges, X, g, s, e)
    Y[(size_t)row * D16 + g] = pack8(m);

    if (row >= R3 && row < R4) {
        uint32_t k2 = k0 ^ k1 ^ 0x1BD11BDAu;
        uint32_t r = (uint32_t)(row * 32 + g);
        maskL[r] = (uint8_t)mask8(k0, k1, k2, r * 8u);
    }
}

// ------- tar SpMM (layers 1,2) + mask [R3,R4) -------------------------------
__global__ void __launch_bounds__(256) spmm_h(
    const int* __restrict__ rowptr, const int2* __restrict__ edges,
    const uint4* __restrict__ X, uint4* __restrict__ Y,
    uint8_t* __restrict__ maskL, uint32_t k0, uint32_t k1)
{
    int row = blockIdx.x * 8 + (threadIdx.x >> 5);
    spmm_body(row, threadIdx.x & 31, rowptr, edges, X, Y, maskL, k0, k1);
}

// ------- MEGA: layer-0 tar SpMM blocks [0,RB) + src scatter blocks [RB,..) --
__global__ void __launch_bounds__(256) spmm_h_mega(
    const int* __restrict__ rowptr, const int2* __restrict__ edges,
    const uint4* __restrict__ X, uint4* __restrict__ Y,
    uint8_t* __restrict__ maskL, uint32_t k0, uint32_t k1,
    const int* __restrict__ src_cols, const float* __restrict__ src_vals,
    const int* __restrict__ rp_s, const uint32_t* __restrict__ rr_s,
    int2* __restrict__ es, int nnz)
{
    if (blockIdx.x < RB) {
        int row = blockIdx.x * 8 + (threadIdx.x >> 5);
        spmm_body(row, threadIdx.x & 31, rowptr, edges, X, Y, maskL, k0, k1);
    } else {
        int t = (blockIdx.x - RB) * 256 + threadIdx.x;
        if (t < nnz) {
            uint32_t rr = __ldcs(rr_s + t);
            int pos = __ldg(rp_s + (rr >> 16)) + (int)(rr & 0xFFFFu);
            es[pos] = make_int2(__ldg(src_cols + t), __float_as_int(__ldg(src_vals + t)));
        }
    }
}

// --- src SpMM fused: residual + dropout + acc (+ final mean) ----------------
// mode 0: v = drop(msg+poi);  x16 = v;  acc = poi + v     (poi f32 residual)
// mode 1: v = drop(msg+x16);  x16 = v;  acc += v
// mode 2: v = drop(msg+x16);  out = (acc + v) * 0.25
__global__ void __launch_bounds__(256) spmm_h_fused(
    const int* __restrict__ rowptr, const int2* __restrict__ edges,
    const uint4* __restrict__ X, const uint8_t* __restrict__ maskL,
    const float4* __restrict__ poi, uint4* __restrict__ x16,
    float4* __restrict__ accbuf, float4* __restrict__ out,
    uint32_t k0, uint32_t k1, int mode)
{
    int row = blockIdx.x * 8 + (threadIdx.x >> 5);
    int g   = threadIdx.x & 31;
    int s = __ldg(rowptr + row), e = __ldg(rowptr + row + 1);

    uint32_t m8;
    if (row < R4) {
        m8 = maskL[row * 32 + g];
    } else {
        uint32_t k2 = k0 ^ k1 ^ 0x1BD11BDAu;
        m8 = mask8(k0, k1, k2, (uint32_t)(row * DIM + g * 8));
    }

    float m[8] = {0.f, 0.f, 0.f, 0.f, 0.f, 0.f, 0.f, 0.f};
    SPMM_LOOP(m, edges, X, g, s, e)

    size_t i4  = (size_t)row * D4 + g * 2;
    size_t i16 = (size_t)row * D16 + g;

    float pv[8];
    if (mode == 0) {
        float4 p0 = __ldg(poi + i4), p1 = __ldg(poi + i4 + 1);
        pv[0] = p0.x; pv[1] = p0.y; pv[2] = p0.z; pv[3] = p0.w;
        pv[4] = p1.x; pv[5] = p1.y; pv[6] = p1.z; pv[7] = p1.w;
    } else {
        unpack8(pv, x16[i16]);
    }

    float v[8];
    #pragma unroll
    for (int t = 0; t < 8; t++)
        v[t] = ((m8 >> t) & 1u) ? (m[t] + pv[t]) * KEEP_INV : 0.0f;

    if (mode == 0) {
        x16[i16] = pack8(v);
        accbuf[i4]     = make_float4(pv[0] + v[0], pv[1] + v[1], pv[2] + v[2], pv[3] + v[3]);
        accbuf[i4 + 1] = make_float4(pv[4] + v[4], pv[5] + v[5], pv[6] + v[6], pv[7] + v[7]);
    } else if (mode == 1) {
        x16[i16] = pack8(v);
        float4 a0 = accbuf[i4], a1 = accbuf[i4 + 1];
        accbuf[i4]     = make_float4(a0.x + v[0], a0.y + v[1], a0.z + v[2], a0.w + v[3]);
        accbuf[i4 + 1] = make_float4(a1.x + v[4], a1.y + v[5], a1.z + v[6], a1.w + v[7]);
    } else {
        float4 a0 = accbuf[i4], a1 = accbuf[i4 + 1];
        out[i4]     = make_float4((a0.x + v[0]) * 0.25f, (a0.y + v[1]) * 0.25f,
                                  (a0.z + v[2]) * 0.25f, (a0.w + v[3]) * 0.25f);
        out[i4 + 1] = make_float4((a1.x + v[4]) * 0.25f, (a1.y + v[5]) * 0.25f,
                                  (a1.z + v[6]) * 0.25f, (a1.w + v[7]) * 0.25f);
    }
}

// ---------------- host-side threefry (per-layer fold_in keys) ---------------
static inline unsigned h_rotl(unsigned x, int r) { return (x << r) | (x >> (32 - r)); }
static void host_threefry(unsigned k0, unsigned k1, unsigned x0, unsigned x1,
                          unsigned* o0, unsigned* o1)
{
    const int rots[2][4] = {{13, 15, 26, 6}, {17, 29, 16, 24}};
    unsigned ks[3] = {k0, k1, k0 ^ k1 ^ 0x1BD11BDAu};
    x0 += ks[0]; x1 += ks[1];
    for (int g = 0; g < 5; g++) {
        for (int j = 0; j < 4; j++) {
            x0 += x1; x1 = h_rotl(x1, rots[g & 1][j]); x1 ^= x0;
        }
        x0 += ks[(g + 1) % 3];
        x1 += ks[(g + 2) % 3] + (unsigned)(g + 1);
    }
    *o0 = x0; *o1 = x1;
}

extern "C" void kernel_launch(void* const* d_in, const int* in_sizes, int n_in,
                              void* d_out, int out_size)
{
    const float* poi     = (const float*)d_in[0];
    const int*   src_row = (const int*)  d_in[1];
    const int*   src_col = (const int*)  d_in[2];
    const float* src_val = (const float*)d_in[3];
    const int*   tar_row = (const int*)  d_in[4];
    const int*   tar_col = (const int*)  d_in[5];
    const float* tar_val = (const float*)d_in[6];
    int nnz = in_sizes[1];

    uint4 *x16, *mt16;
    float4 *acc;
    uint8_t *mask;
    int *rp_s, *rp_t, *cnt;
    uint32_t *rr_t, *rr_s;
    int2 *es, *et;
    cudaGetSymbolAddress((void**)&x16,  g_x16);
    cudaGetSymbolAddress((void**)&mt16, g_mt16);
    cudaGetSymbolAddress((void**)&acc,  g_acc);
    cudaGetSymbolAddress((void**)&mask, g_mask);
    cudaGetSymbolAddress((void**)&rp_s, g_rp_src);
    cudaGetSymbolAddress((void**)&rp_t, g_rp_tar);
    cudaGetSymbolAddress((void**)&cnt,  g_cnt);
    cudaGetSymbolAddress((void**)&rr_t, g_rr_t);
    cudaGetSymbolAddress((void**)&rr_s, g_rr_s);
    cudaGetSymbolAddress((void**)&es,   g_e_src);
    cudaGetSymbolAddress((void**)&et,   g_e_tar);

    unsigned lk0[3], lk1[3];
    for (unsigned i = 0; i < 3; i++)
        host_threefry(0u, 42u, 0u, i, &lk0[i], &lk1[i]);

    int nthreads = nnz > NPOI * D16 ? nnz : NPOI * D16;
    int eb  = (nthreads + 255) / 256;
    int ebs = (nnz + 255) / 256;

    // ---- fused CSR build (+ fp16 snapshot + mask rows [0,R3) x 3 layers) ---
    cudaMemsetAsync(cnt, 0, 2 * NPOI * sizeof(int), 0);
    hist2_kernel<<<eb, 256>>>(tar_row, src_row, cnt, rr_t, rr_s,
                              (const float4*)poi, x16, mask, nnz,
                              lk0[0], lk1[0], lk0[1], lk1[1], lk0[2], lk1[2]);
    scan2_kernel<<<148, 1024>>>(cnt, rp_t, rp_s, mask,
                                lk0[0], lk1[0], lk0[1], lk1[1], lk0[2], lk1[2]);
    scatter_tar_kernel<<<ebs, 256>>>(tar_col, tar_val, rp_t, rr_t, et, mask, nnz,
                                     lk0[0], lk1[0], lk0[1], lk1[1], lk0[2], lk1[2]);

    // ---- layer 0: MEGA (tar SpMM + hidden src scatter), then fused ----------
    spmm_h_mega<<<RB + ebs, 256>>>(rp_t, et, x16, mt16, mask, lk0[0], lk1[0],
                                   src_col, src_val, rp_s, rr_s, es, nnz);
    spmm_h_fused<<<RB, 256>>>(rp_s, es, mt16, mask,
                              (const float4*)poi, x16, acc, (float4*)d_out,
                              lk0[0], lk1[0], 0);

    // ---- layers 1, 2 --------------------------------------------------------
    for (int i = 1; i < 3; i++) {
        uint8_t* maskL = mask + (size_t)i * MASKB;
        spmm_h<<<RB, 256>>>(rp_t, et, x16, mt16, maskL, lk0[i], lk1[i]);
        spmm_h_fused<<<RB, 256>>>(rp_s, es, mt16, maskL,
                                  (const float4*)poi, x16, acc, (float4*)d_out,
                                  lk0[i], lk1[i], i);
    }
}